// round 15
// baseline (speedup 1.0000x reference)
#include <cuda_runtime.h>
#include <cuda_bf16.h>
#include <cstdint>

#define NNODES  50000
#define MAXE    800000
#define HID     128
#define INDIM   768
#define NGRAPH  128
#define NCLS    3
#define NSCANB  196             // ceil(50000/256)

// GEMM tiling: BM=128, BN=128, BK=32
#define BK      32
#define ASTRIDE 80
#define ABUF    10240           // 128 * 80
#define BBUF    10240
#define BUFSZ   40960           // 2*ABUF + 2*BBUF
#define MMA_SMEM (2 * BUFSZ)    // 81920

// ---------------- scratch -------------------------------------------------
__device__ float g_h  [NNODES * HID];   // h0a  / h1
__device__ float g_h2 [NNODES * HID];   // h0b (split-K partial)
__device__ float g_hs [NNODES * HID];
__device__ float g_dinv[NNODES];
__device__ int   g_deg [NNODES];
__device__ int   g_start[NNODES + 1];
__device__ int   g_cursor[NNODES];
__device__ int   g_bsum[NSCANB];
__device__ int   g_csr [MAXE];
__device__ float g_pool[NGRAPH * HID + NGRAPH];
__device__ __nv_bfloat16 g_Wemb_h[HID * INDIM], g_Wemb_l[HID * INDIM];
__device__ __nv_bfloat16 g_Wc1_h [HID * HID],   g_Wc1_l [HID * HID];
__device__ __nv_bfloat16 g_Wc2_h [HID * HID],   g_Wc2_l [HID * HID];

// ---------------- helpers -------------------------------------------------
__device__ __forceinline__ uint32_t s2u(const void *p) {
    uint32_t a;
    asm("{ .reg .u64 t; cvta.to.shared.u64 t, %1; cvt.u32.u64 %0, t; }"
        : "=r"(a) : "l"(p));
    return a;
}
__device__ __forceinline__ void red4(float *p, float4 v) {
    asm volatile("red.global.add.v4.f32 [%0], {%1, %2, %3, %4};"
                 :: "l"(p), "f"(v.x), "f"(v.y), "f"(v.z), "f"(v.w) : "memory");
}
__device__ __forceinline__ void ldsm4(uint32_t &r0, uint32_t &r1, uint32_t &r2,
                                      uint32_t &r3, uint32_t addr) {
    asm volatile("ldmatrix.sync.aligned.m8n8.x4.shared.b16 {%0,%1,%2,%3}, [%4];"
                 : "=r"(r0), "=r"(r1), "=r"(r2), "=r"(r3) : "r"(addr));
}
__device__ __forceinline__ void mma16816(float *c, const uint32_t *a,
                                         const uint32_t *b) {
    asm volatile(
        "mma.sync.aligned.m16n8k16.row.col.f32.bf16.bf16.f32 "
        "{%0,%1,%2,%3}, {%4,%5,%6,%7}, {%8,%9}, {%0,%1,%2,%3};"
        : "+f"(c[0]), "+f"(c[1]), "+f"(c[2]), "+f"(c[3])
        : "r"(a[0]), "r"(a[1]), "r"(a[2]), "r"(a[3]), "r"(b[0]), "r"(b[1]));
}
__device__ __forceinline__ void cpa16(uint32_t s, const void *g) {
    asm volatile("cp.async.cg.shared.global [%0], [%1], 16;" :: "r"(s), "l"(g));
}
__device__ __forceinline__ void cvt8(const float4 &v0, const float4 &v1,
                                     uint4 &hv, uint4 &lv) {
    __nv_bfloat162 h0 = __floats2bfloat162_rn(v0.x, v0.y);
    __nv_bfloat162 h1 = __floats2bfloat162_rn(v0.z, v0.w);
    __nv_bfloat162 h2 = __floats2bfloat162_rn(v1.x, v1.y);
    __nv_bfloat162 h3 = __floats2bfloat162_rn(v1.z, v1.w);
    __nv_bfloat162 l0 = __floats2bfloat162_rn(v0.x - __bfloat162float(h0.x),
                                              v0.y - __bfloat162float(h0.y));
    __nv_bfloat162 l1 = __floats2bfloat162_rn(v0.z - __bfloat162float(h1.x),
                                              v0.w - __bfloat162float(h1.y));
    __nv_bfloat162 l2 = __floats2bfloat162_rn(v1.x - __bfloat162float(h2.x),
                                              v1.y - __bfloat162float(h2.y));
    __nv_bfloat162 l3 = __floats2bfloat162_rn(v1.z - __bfloat162float(h3.x),
                                              v1.w - __bfloat162float(h3.y));
    hv = make_uint4(*(uint32_t *)&h0, *(uint32_t *)&h1,
                    *(uint32_t *)&h2, *(uint32_t *)&h3);
    lv = make_uint4(*(uint32_t *)&l0, *(uint32_t *)&l1,
                    *(uint32_t *)&l2, *(uint32_t *)&l3);
}

// ---------------- misc small kernels --------------------------------------
__global__ void k_zero4(float4 *__restrict__ p, int n4) {
    int i = blockIdx.x * blockDim.x + threadIdx.x;
    if (i < n4) p[i] = make_float4(0.f, 0.f, 0.f, 0.f);
}
__global__ void k_zero_deg(int *__restrict__ p, int n) {
    int i = blockIdx.x * blockDim.x + threadIdx.x;
    if (i < n) p[i] = 0;
}
__global__ void k_deg(const int *__restrict__ ei, int E) {
    int i = blockIdx.x * blockDim.x + threadIdx.x;
    if (i < E) atomicAdd(&g_deg[ei[E + i]], 1);
}
__global__ void k_dinv(int N) {
    int i = blockIdx.x * blockDim.x + threadIdx.x;
    if (i < N) g_dinv[i] = rsqrtf((float)g_deg[i] + 1.0f);
}

// ---------------- CSR build -----------------------------------------------
__global__ void k_scan1(int N) {
    __shared__ int sh[256];
    int i = blockIdx.x * 256 + threadIdx.x;
    int v = (i < N) ? g_deg[i] : 0;
    sh[threadIdx.x] = v;
    __syncthreads();
    int x = v;
#pragma unroll
    for (int o = 1; o < 256; o <<= 1) {
        int y = (threadIdx.x >= o) ? sh[threadIdx.x - o] : 0;
        __syncthreads();
        x += y; sh[threadIdx.x] = x;
        __syncthreads();
    }
    if (i < N) g_start[i] = x - v;
    if (threadIdx.x == 255) g_bsum[blockIdx.x] = x;
}
__global__ void k_scan2() {
    __shared__ int sh[256];
    int v = (threadIdx.x < NSCANB) ? g_bsum[threadIdx.x] : 0;
    sh[threadIdx.x] = v;
    __syncthreads();
    int x = v;
#pragma unroll
    for (int o = 1; o < 256; o <<= 1) {
        int y = (threadIdx.x >= o) ? sh[threadIdx.x - o] : 0;
        __syncthreads();
        x += y; sh[threadIdx.x] = x;
        __syncthreads();
    }
    if (threadIdx.x < NSCANB) g_bsum[threadIdx.x] = x - v;
}
__global__ void k_scan3(int N, int E) {
    int i = blockIdx.x * 256 + threadIdx.x;
    if (i < N) {
        int s = g_start[i] + g_bsum[i >> 8];
        g_start[i] = s;
        g_cursor[i] = s;
    }
    if (i == 0) g_start[N] = E;
}
__global__ void k_fill(const int *__restrict__ ei, int E) {
    int i = blockIdx.x * blockDim.x + threadIdx.x;
    if (i >= E) return;
    int d = ei[E + i];
    int pos = atomicAdd(&g_cursor[d], 1);
    g_csr[pos] = ei[i];
}

// ---------------- W prep --------------------------------------------------
__global__ void k_prepW(const float *__restrict__ W, __nv_bfloat16 *__restrict__ Bh,
                        __nv_bfloat16 *__restrict__ Bl, int K) {
    int i = blockIdx.x * blockDim.x + threadIdx.x;
    if (i >= K * HID) return;
    int k = i / HID, n = i % HID;
    float v = W[i];
    __nv_bfloat16 h = __float2bfloat16(v);
    __nv_bfloat16 l = __float2bfloat16(v - __bfloat162float(h));
    Bh[(size_t)n * K + k] = h;
    Bl[(size_t)n * K + k] = l;
}

// ---------------- HMMA GEMM (BM=128, double-buffered, cp.async) ------------
// C[M,128] = (A[:,koff:koff+keff] (+A2)) @ Bt[:,koff:koff+keff]^T * dinv + bias
// A row stride = Kst. A2 optional second addend matrix (same layout).
__global__ void __launch_bounds__(256, 2)
hmma_gemm(const float *__restrict__ A, const float *__restrict__ A2,
          const __nv_bfloat16 *__restrict__ Bhg,
          const __nv_bfloat16 *__restrict__ Blg,
          const float *__restrict__ bias, const float *__restrict__ dinv,
          float *__restrict__ C, int M, int Kst, int koff, int keff)
{
    extern __shared__ __align__(1024) char smem[];
    const uint32_t sb = s2u(smem);
    const int tid = threadIdx.x;
    const int wid = tid >> 5, lane = tid & 31;
    const int warp_m = wid & 3, warp_n = wid >> 2;
    const int bm0 = blockIdx.x * 128;

    const int alr = tid >> 1, alq = tid & 1;
    int arow = bm0 + alr; if (arow >= M) arow = M - 1;
    const float *Ar  = A + (size_t)arow * Kst + koff + alq * 16;
    const float *A2r = A2 ? A2 + (size_t)arow * Kst + koff + alq * 16 : nullptr;
    const uint32_t a_sts = (uint32_t)(alr * ASTRIDE + alq * 32);

    const int bln = tid >> 1, blu = tid & 1;
    const __nv_bfloat16 *Bhr = Bhg + (size_t)bln * Kst + koff + blu * 16;
    const __nv_bfloat16 *Blr = Blg + (size_t)bln * Kst + koff + blu * 16;
    const uint32_t b_sts = (uint32_t)(bln * ASTRIDE + blu * 32);

    const int sub = lane >> 3, lr8 = lane & 7;
    uint32_t a_off[2], b_off[4];
#pragma unroll
    for (int mi = 0; mi < 2; ++mi) {
        int row = warp_m * 32 + mi * 16 + ((sub & 1) << 3) + lr8;
        a_off[mi] = (uint32_t)(row * ASTRIDE + ((sub >> 1) << 4));
    }
#pragma unroll
    for (int np = 0; np < 4; ++np) {
        int nr = warp_n * 64 + np * 16 + ((sub >> 1) << 3) + lr8;
        b_off[np] = (uint32_t)(nr * ASTRIDE + ((sub & 1) << 4));
    }

    float acc[2][8][4];
#pragma unroll
    for (int mi = 0; mi < 2; ++mi)
#pragma unroll
        for (int ni = 0; ni < 8; ++ni)
#pragma unroll
            for (int q = 0; q < 4; ++q) acc[mi][ni][q] = 0.f;

    const int NC = keff / BK;
    float4 va0, va1, va2, va3;

    auto loadA = [&](int k1) {
        va0 = *(const float4 *)(Ar + k1);
        va1 = *(const float4 *)(Ar + k1 + 4);
        va2 = *(const float4 *)(Ar + k1 + 8);
        va3 = *(const float4 *)(Ar + k1 + 12);
        if (A2r) {
            float4 w0 = *(const float4 *)(A2r + k1);
            float4 w1 = *(const float4 *)(A2r + k1 + 4);
            float4 w2 = *(const float4 *)(A2r + k1 + 8);
            float4 w3 = *(const float4 *)(A2r + k1 + 12);
            va0.x += w0.x; va0.y += w0.y; va0.z += w0.z; va0.w += w0.w;
            va1.x += w1.x; va1.y += w1.y; va1.z += w1.z; va1.w += w1.w;
            va2.x += w2.x; va2.y += w2.y; va2.z += w2.z; va2.w += w2.w;
            va3.x += w3.x; va3.y += w3.y; va3.z += w3.z; va3.w += w3.w;
        }
    };

    // ---- prologue ----
    loadA(0);
    {
        uint32_t s0 = sb + 2 * ABUF + b_sts;
        cpa16(s0,             Bhr);
        cpa16(s0 + 16,        Bhr + 8);
        cpa16(s0 + BBUF,      Blr);
        cpa16(s0 + BBUF + 16, Blr + 8);
        asm volatile("cp.async.commit_group;" ::: "memory");
    }
    {
        uint4 hv, lv;
        cvt8(va0, va1, hv, lv);
        *(uint4 *)(smem + a_sts)        = hv;
        *(uint4 *)(smem + ABUF + a_sts) = lv;
        cvt8(va2, va3, hv, lv);
        *(uint4 *)(smem + a_sts + 16)        = hv;
        *(uint4 *)(smem + ABUF + a_sts + 16) = lv;
    }
    asm volatile("cp.async.wait_group 0;" ::: "memory");
    __syncthreads();

    for (int c = 0; c < NC; ++c) {
        const uint32_t bo = (c & 1) ? (uint32_t)BUFSZ : 0u;
        const uint32_t bn = (c & 1) ? 0u : (uint32_t)BUFSZ;
        const bool more = (c + 1 < NC);
        if (more) {
            const int k1 = (c + 1) * BK;
            loadA(k1);
            uint32_t s0 = sb + bn + 2 * ABUF + b_sts;
            cpa16(s0,             Bhr + k1);
            cpa16(s0 + 16,        Bhr + k1 + 8);
            cpa16(s0 + BBUF,      Blr + k1);
            cpa16(s0 + BBUF + 16, Blr + k1 + 8);
            asm volatile("cp.async.commit_group;" ::: "memory");
        }

#pragma unroll
        for (int ks = 0; ks < 2; ++ks) {
            uint32_t ahi[2][4], alo[2][4];
#pragma unroll
            for (int mi = 0; mi < 2; ++mi) {
                uint32_t ad = sb + bo + a_off[mi] + ks * 32;
                ldsm4(ahi[mi][0], ahi[mi][1], ahi[mi][2], ahi[mi][3], ad);
                ldsm4(alo[mi][0], alo[mi][1], alo[mi][2], alo[mi][3], ad + ABUF);
            }
#pragma unroll
            for (int np = 0; np < 4; ++np) {
                uint32_t bhi[2][2], blo[2][2];
                uint32_t bd = sb + bo + 2 * ABUF + b_off[np] + ks * 32;
                ldsm4(bhi[0][0], bhi[0][1], bhi[1][0], bhi[1][1], bd);
                ldsm4(blo[0][0], blo[0][1], blo[1][0], blo[1][1], bd + BBUF);
#pragma unroll
                for (int mi = 0; mi < 2; ++mi)
#pragma unroll
                    for (int h = 0; h < 2; ++h)
                        mma16816(acc[mi][np * 2 + h], ahi[mi], bhi[h]);
#pragma unroll
                for (int mi = 0; mi < 2; ++mi)
#pragma unroll
                    for (int h = 0; h < 2; ++h)
                        mma16816(acc[mi][np * 2 + h], ahi[mi], blo[h]);
#pragma unroll
                for (int mi = 0; mi < 2; ++mi)
#pragma unroll
                    for (int h = 0; h < 2; ++h)
                        mma16816(acc[mi][np * 2 + h], alo[mi], bhi[h]);
            }
        }

        if (more) {
            uint4 hv, lv;
            cvt8(va0, va1, hv, lv);
            *(uint4 *)(smem + bn + a_sts)        = hv;
            *(uint4 *)(smem + bn + ABUF + a_sts) = lv;
            cvt8(va2, va3, hv, lv);
            *(uint4 *)(smem + bn + a_sts + 16)        = hv;
            *(uint4 *)(smem + bn + ABUF + a_sts + 16) = lv;
            asm volatile("cp.async.wait_group 0;" ::: "memory");
        }
        __syncthreads();
    }

    // ---- epilogue ----
    const int gid = lane >> 2, qid = lane & 3;
#pragma unroll
    for (int mi = 0; mi < 2; ++mi) {
        int row0 = bm0 + warp_m * 32 + mi * 16 + gid;
        int row1 = row0 + 8;
        float s0 = 1.f, s1 = 1.f;
        if (dinv) {
            if (row0 < M) s0 = dinv[row0];
            if (row1 < M) s1 = dinv[row1];
        }
#pragma unroll
        for (int ni = 0; ni < 8; ++ni) {
            int col = warp_n * 64 + ni * 8 + qid * 2;
            float b0 = 0.f, b1 = 0.f;
            if (bias) { b0 = bias[col]; b1 = bias[col + 1]; }
            if (row0 < M) {
                float2 o = make_float2(fmaf(acc[mi][ni][0], s0, b0),
                                       fmaf(acc[mi][ni][1], s0, b1));
                *(float2 *)&C[(size_t)row0 * HID + col] = o;
            }
            if (row1 < M) {
                float2 o = make_float2(fmaf(acc[mi][ni][2], s1, b0),
                                       fmaf(acc[mi][ni][3], s1, b1));
                *(float2 *)&C[(size_t)row1 * HID + col] = o;
            }
        }
    }
}

// ---------------- CSR aggregate: warp per node -----------------------------
// hs pre-scaled by source dinv.  out = dinv_d*(sum + self) + bias
__global__ void __launch_bounds__(256)
k_agg(const float *__restrict__ hs, const float *__restrict__ bias,
      float *__restrict__ outp, const int *__restrict__ batch,
      float *__restrict__ pool, int relu, int pool_mode, int N)
{
    int node = (blockIdx.x * blockDim.x + threadIdx.x) >> 5;
    if (node >= N) return;
    int lane = threadIdx.x & 31;
    int c = lane * 4;

    int e0 = g_start[node], e1 = g_start[node + 1];
    float4 acc = *(const float4 *)&hs[(size_t)node * HID + c];

    int e = e0;
    for (; e + 4 <= e1; e += 4) {
        int i0 = g_csr[e], i1 = g_csr[e + 1], i2 = g_csr[e + 2], i3 = g_csr[e + 3];
        float4 v0 = *(const float4 *)&hs[(size_t)i0 * HID + c];
        float4 v1 = *(const float4 *)&hs[(size_t)i1 * HID + c];
        float4 v2 = *(const float4 *)&hs[(size_t)i2 * HID + c];
        float4 v3 = *(const float4 *)&hs[(size_t)i3 * HID + c];
        acc.x += v0.x + v1.x + v2.x + v3.x;
        acc.y += v0.y + v1.y + v2.y + v3.y;
        acc.z += v0.z + v1.z + v2.z + v3.z;
        acc.w += v0.w + v1.w + v2.w + v3.w;
    }
    for (; e < e1; ++e) {
        int i0 = g_csr[e];
        float4 v0 = *(const float4 *)&hs[(size_t)i0 * HID + c];
        acc.x += v0.x; acc.y += v0.y; acc.z += v0.z; acc.w += v0.w;
    }

    float dv = g_dinv[node];
    float4 b = *(const float4 *)&bias[c];
    float4 o;
    o.x = fmaf(dv, acc.x, b.x);
    o.y = fmaf(dv, acc.y, b.y);
    o.z = fmaf(dv, acc.z, b.z);
    o.w = fmaf(dv, acc.w, b.w);
    if (relu) {
        o.x = fmaxf(o.x, 0.f); o.y = fmaxf(o.y, 0.f);
        o.z = fmaxf(o.z, 0.f); o.w = fmaxf(o.w, 0.f);
    }
    if (pool_mode) {
        int g = batch[node];
        red4(&pool[(size_t)g * HID + c], o);
        if (lane == 0) atomicAdd(&pool[NGRAPH * HID + g], 1.0f);
    } else {
        *(float4 *)&outp[(size_t)node * HID + c] = o;
    }
}

// ---------------- head MLP -------------------------------------------------
__global__ void k_head(const float *__restrict__ pool,
                       const float *__restrict__ W1, const float *__restrict__ b1,
                       const float *__restrict__ W2, const float *__restrict__ b2,
                       float *__restrict__ out)
{
    __shared__ float gv[HID];
    __shared__ float hid[HID];
    int g = blockIdx.x, t = threadIdx.x;
    float cnt = fmaxf(pool[NGRAPH * HID + g], 1.0f);
    gv[t] = pool[(size_t)g * HID + t] / cnt;
    __syncthreads();
    float acc = b1[t];
#pragma unroll 8
    for (int c = 0; c < HID; ++c) acc = fmaf(gv[c], W1[c * HID + t], acc);
    hid[t] = fmaxf(acc, 0.f);
    __syncthreads();
    if (t < NCLS) {
        float o = b2[t];
#pragma unroll 8
        for (int hh = 0; hh < HID; ++hh) o = fmaf(hid[hh], W2[hh * NCLS + t], o);
        out[g * NCLS + t] = o;
    }
}

// ---------------- launcher -------------------------------------------------
extern "C" void kernel_launch(void *const *d_in, const int *in_sizes, int n_in,
                              void *d_out, int out_size)
{
    const float *x     = (const float *)d_in[0];
    const int   *ei    = (const int *)d_in[1];
    const int   *batch = (const int *)d_in[2];
    const float *W_emb = (const float *)d_in[3], *b_emb = (const float *)d_in[4];
    const float *W_c1  = (const float *)d_in[5], *b_c1  = (const float *)d_in[6];
    const float *W_c2  = (const float *)d_in[7], *b_c2  = (const float *)d_in[8];
    const float *W_l1  = (const float *)d_in[9], *b_l1  = (const float *)d_in[10];
    const float *W_l2  = (const float *)d_in[11], *b_l2 = (const float *)d_in[12];
    float *out = (float *)d_out;

    const int E = in_sizes[1] / 2;
    const int N = in_sizes[2];
    const int K_IN = in_sizes[0] / N;
    const int K_HALF = K_IN / 2;

    static float *p_h = nullptr, *p_h2 = nullptr, *p_hs = nullptr,
                 *p_dinv = nullptr, *p_pool = nullptr;
    static int *p_deg = nullptr;
    static __nv_bfloat16 *p_We_h, *p_We_l, *p_W1_h, *p_W1_l, *p_W2_h, *p_W2_l;
    static cudaStream_t s2 = nullptr, s3 = nullptr;
    static cudaEvent_t evFork = nullptr, evJoin = nullptr, evW = nullptr,
                       evG1 = nullptr;
    if (!p_h) {
        cudaGetSymbolAddress((void **)&p_h,    g_h);
        cudaGetSymbolAddress((void **)&p_h2,   g_h2);
        cudaGetSymbolAddress((void **)&p_hs,   g_hs);
        cudaGetSymbolAddress((void **)&p_dinv, g_dinv);
        cudaGetSymbolAddress((void **)&p_pool, g_pool);
        cudaGetSymbolAddress((void **)&p_deg,  g_deg);
        cudaGetSymbolAddress((void **)&p_We_h, g_Wemb_h);
        cudaGetSymbolAddress((void **)&p_We_l, g_Wemb_l);
        cudaGetSymbolAddress((void **)&p_W1_h, g_Wc1_h);
        cudaGetSymbolAddress((void **)&p_W1_l, g_Wc1_l);
        cudaGetSymbolAddress((void **)&p_W2_h, g_Wc2_h);
        cudaGetSymbolAddress((void **)&p_W2_l, g_Wc2_l);
        cudaFuncSetAttribute(hmma_gemm,
                             cudaFuncAttributeMaxDynamicSharedMemorySize, MMA_SMEM);
        cudaStreamCreateWithFlags(&s2, cudaStreamNonBlocking);
        cudaStreamCreateWithFlags(&s3, cudaStreamNonBlocking);
        cudaEventCreateWithFlags(&evFork, cudaEventDisableTiming);
        cudaEventCreateWithFlags(&evJoin, cudaEventDisableTiming);
        cudaEventCreateWithFlags(&evW,    cudaEventDisableTiming);
        cudaEventCreateWithFlags(&evG1,   cudaEventDisableTiming);
    }

    const int mma_grid  = (N + 127) / 128;
    const int agg_grid  = (N * 32 + 255) / 256;

    // ---- fork ----
    cudaEventRecord(evFork, 0);
    cudaStreamWaitEvent(s2, evFork, 0);
    cudaStreamWaitEvent(s3, evFork, 0);

    // side chain on s2: CSR + dinv + conv weight prep + pool zero
    k_zero_deg<<<(N + 255) / 256, 256, 0, s2>>>(p_deg, N);
    k_deg <<<(E + 255) / 256, 256, 0, s2>>>(ei, E);
    k_dinv<<<(N + 255) / 256, 256, 0, s2>>>(N);
    k_scan1<<<NSCANB, 256, 0, s2>>>(N);
    k_scan2<<<1, 256, 0, s2>>>();
    k_scan3<<<(N + 255) / 256, 256, 0, s2>>>(N, E);
    k_fill <<<(E + 255) / 256, 256, 0, s2>>>(ei, E);
    k_prepW<<<(HID * HID + 255) / 256, 256, 0, s2>>>(W_c1, p_W1_h, p_W1_l, HID);
    k_prepW<<<(HID * HID + 255) / 256, 256, 0, s2>>>(W_c2, p_W2_h, p_W2_l, HID);
    k_zero4<<<(NGRAPH * (HID + 1) / 4 + 255) / 256, 256, 0, s2>>>(
        (float4 *)p_pool, NGRAPH * (HID + 1) / 4);

    // main: Wemb prep, then GEMM1 split-K half0; half1 on s3 concurrently
    k_prepW<<<(K_IN * HID + 255) / 256, 256>>>(W_emb, p_We_h, p_We_l, K_IN);
    cudaEventRecord(evW, 0);
    cudaStreamWaitEvent(s3, evW, 0);

    hmma_gemm<<<mma_grid, 256, MMA_SMEM>>>(x, nullptr, p_We_h, p_We_l,
                                           b_emb, nullptr, p_h,
                                           N, K_IN, 0, K_HALF);
    hmma_gemm<<<mma_grid, 256, MMA_SMEM, s3>>>(x, nullptr, p_We_h, p_We_l,
                                               nullptr, nullptr, p_h2,
                                               N, K_IN, K_HALF, K_HALF);
    cudaEventRecord(evG1, s3);

    // ---- join (conv1 gemm needs h0a+h0b, Wc1, dinv) ----
    cudaEventRecord(evJoin, s2);
    cudaStreamWaitEvent(0, evJoin, 0);
    cudaStreamWaitEvent(0, evG1, 0);

    // conv1: hs = dinv * ((h0a+h0b) @ Wc1)
    hmma_gemm<<<mma_grid, 256, MMA_SMEM>>>(p_h, p_h2, p_W1_h, p_W1_l,
                                           nullptr, p_dinv, p_hs,
                                           N, HID, 0, HID);
    k_agg<<<agg_grid, 256>>>(p_hs, b_c1, p_h, nullptr, nullptr, 1, 0, N);

    // conv2: hs = dinv * (h1 @ Wc2); fused agg + pool
    hmma_gemm<<<mma_grid, 256, MMA_SMEM>>>(p_h, nullptr, p_W2_h, p_W2_l,
                                           nullptr, p_dinv, p_hs,
                                           N, HID, 0, HID);
    k_agg<<<agg_grid, 256>>>(p_hs, b_c2, nullptr, batch, p_pool, 0, 1, N);

    // head
    k_head<<<NGRAPH, HID>>>(p_pool, W_l1, b_l1, W_l2, b_l2, out);
}

// round 16
// speedup vs baseline: 1.1603x; 1.1603x over previous
#include <cuda_runtime.h>
#include <cuda_bf16.h>
#include <cuda_fp16.h>
#include <cstdint>

#define NNODES  50000
#define MAXE    800000
#define HID     128
#define INDIM   768
#define NGRAPH  128
#define NCLS    3
#define NSCANB  196             // ceil(50000/256)

// GEMM tiling: BM=128, BN=128, BK=32
#define BK      32
#define ASTRIDE 80
#define ABUF    10240           // 128 * 80
#define BBUF    10240
#define BUFSZ   40960           // 2*ABUF + 2*BBUF
#define MMA_SMEM (2 * BUFSZ)    // 81920

// ---------------- scratch -------------------------------------------------
__device__ float  g_h   [NNODES * HID];     // h0 / h1 (fp32)
__device__ __half g_hsh [NNODES * HID];     // hs intermediate (fp16)
__device__ float  g_dinv[NNODES];
__device__ int    g_deg [NNODES];
__device__ int    g_start[NNODES + 1];
__device__ int    g_cursor[NNODES];
__device__ int    g_bsum[NSCANB];
__device__ int    g_csr [MAXE];
__device__ float  g_pool[NGRAPH * HID + NGRAPH];
__device__ __nv_bfloat16 g_Wemb_h[HID * INDIM], g_Wemb_l[HID * INDIM];
__device__ __nv_bfloat16 g_Wc1_h [HID * HID],   g_Wc1_l [HID * HID];
__device__ __nv_bfloat16 g_Wc2_h [HID * HID],   g_Wc2_l [HID * HID];

// ---------------- helpers -------------------------------------------------
__device__ __forceinline__ uint32_t s2u(const void *p) {
    uint32_t a;
    asm("{ .reg .u64 t; cvta.to.shared.u64 t, %1; cvt.u32.u64 %0, t; }"
        : "=r"(a) : "l"(p));
    return a;
}
__device__ __forceinline__ void red4(float *p, float4 v) {
    asm volatile("red.global.add.v4.f32 [%0], {%1, %2, %3, %4};"
                 :: "l"(p), "f"(v.x), "f"(v.y), "f"(v.z), "f"(v.w) : "memory");
}
__device__ __forceinline__ void ldsm4(uint32_t &r0, uint32_t &r1, uint32_t &r2,
                                      uint32_t &r3, uint32_t addr) {
    asm volatile("ldmatrix.sync.aligned.m8n8.x4.shared.b16 {%0,%1,%2,%3}, [%4];"
                 : "=r"(r0), "=r"(r1), "=r"(r2), "=r"(r3) : "r"(addr));
}
__device__ __forceinline__ void mma16816(float *c, const uint32_t *a,
                                         const uint32_t *b) {
    asm volatile(
        "mma.sync.aligned.m16n8k16.row.col.f32.bf16.bf16.f32 "
        "{%0,%1,%2,%3}, {%4,%5,%6,%7}, {%8,%9}, {%0,%1,%2,%3};"
        : "+f"(c[0]), "+f"(c[1]), "+f"(c[2]), "+f"(c[3])
        : "r"(a[0]), "r"(a[1]), "r"(a[2]), "r"(a[3]), "r"(b[0]), "r"(b[1]));
}
__device__ __forceinline__ void cpa16(uint32_t s, const void *g) {
    asm volatile("cp.async.cg.shared.global [%0], [%1], 16;" :: "r"(s), "l"(g));
}
__device__ __forceinline__ void cvt8(const float4 &v0, const float4 &v1,
                                     uint4 &hv, uint4 &lv) {
    __nv_bfloat162 h0 = __floats2bfloat162_rn(v0.x, v0.y);
    __nv_bfloat162 h1 = __floats2bfloat162_rn(v0.z, v0.w);
    __nv_bfloat162 h2 = __floats2bfloat162_rn(v1.x, v1.y);
    __nv_bfloat162 h3 = __floats2bfloat162_rn(v1.z, v1.w);
    __nv_bfloat162 l0 = __floats2bfloat162_rn(v0.x - __bfloat162float(h0.x),
                                              v0.y - __bfloat162float(h0.y));
    __nv_bfloat162 l1 = __floats2bfloat162_rn(v0.z - __bfloat162float(h1.x),
                                              v0.w - __bfloat162float(h1.y));
    __nv_bfloat162 l2 = __floats2bfloat162_rn(v1.x - __bfloat162float(h2.x),
                                              v1.y - __bfloat162float(h2.y));
    __nv_bfloat162 l3 = __floats2bfloat162_rn(v1.z - __bfloat162float(h3.x),
                                              v1.w - __bfloat162float(h3.y));
    hv = make_uint4(*(uint32_t *)&h0, *(uint32_t *)&h1,
                    *(uint32_t *)&h2, *(uint32_t *)&h3);
    lv = make_uint4(*(uint32_t *)&l0, *(uint32_t *)&l1,
                    *(uint32_t *)&l2, *(uint32_t *)&l3);
}

// ---------------- misc small kernels --------------------------------------
__global__ void k_zero4(float4 *__restrict__ p, int n4) {
    int i = blockIdx.x * blockDim.x + threadIdx.x;
    if (i < n4) p[i] = make_float4(0.f, 0.f, 0.f, 0.f);
}
__global__ void k_zero_deg(int *__restrict__ p, int n) {
    int i = blockIdx.x * blockDim.x + threadIdx.x;
    if (i < n) p[i] = 0;
}
__global__ void k_deg(const int *__restrict__ ei, int E) {
    int i = blockIdx.x * blockDim.x + threadIdx.x;
    if (i < E) atomicAdd(&g_deg[ei[E + i]], 1);
}
__global__ void k_dinv(int N) {
    int i = blockIdx.x * blockDim.x + threadIdx.x;
    if (i < N) g_dinv[i] = rsqrtf((float)g_deg[i] + 1.0f);
}

// ---------------- CSR build -----------------------------------------------
__global__ void k_scan1(int N) {
    __shared__ int sh[256];
    int i = blockIdx.x * 256 + threadIdx.x;
    int v = (i < N) ? g_deg[i] : 0;
    sh[threadIdx.x] = v;
    __syncthreads();
    int x = v;
#pragma unroll
    for (int o = 1; o < 256; o <<= 1) {
        int y = (threadIdx.x >= o) ? sh[threadIdx.x - o] : 0;
        __syncthreads();
        x += y; sh[threadIdx.x] = x;
        __syncthreads();
    }
    if (i < N) g_start[i] = x - v;
    if (threadIdx.x == 255) g_bsum[blockIdx.x] = x;
}
__global__ void k_scan2() {
    __shared__ int sh[256];
    int v = (threadIdx.x < NSCANB) ? g_bsum[threadIdx.x] : 0;
    sh[threadIdx.x] = v;
    __syncthreads();
    int x = v;
#pragma unroll
    for (int o = 1; o < 256; o <<= 1) {
        int y = (threadIdx.x >= o) ? sh[threadIdx.x - o] : 0;
        __syncthreads();
        x += y; sh[threadIdx.x] = x;
        __syncthreads();
    }
    if (threadIdx.x < NSCANB) g_bsum[threadIdx.x] = x - v;
}
__global__ void k_scan3(int N, int E) {
    int i = blockIdx.x * 256 + threadIdx.x;
    if (i < N) {
        int s = g_start[i] + g_bsum[i >> 8];
        g_start[i] = s;
        g_cursor[i] = s;
    }
    if (i == 0) g_start[N] = E;
}
__global__ void k_fill(const int *__restrict__ ei, int E) {
    int i = blockIdx.x * blockDim.x + threadIdx.x;
    if (i >= E) return;
    int d = ei[E + i];
    int pos = atomicAdd(&g_cursor[d], 1);
    g_csr[pos] = ei[i];
}

// ---------------- W prep --------------------------------------------------
__global__ void k_prepW(const float *__restrict__ W, __nv_bfloat16 *__restrict__ Bh,
                        __nv_bfloat16 *__restrict__ Bl, int K) {
    int i = blockIdx.x * blockDim.x + threadIdx.x;
    if (i >= K * HID) return;
    int k = i / HID, n = i % HID;
    float v = W[i];
    __nv_bfloat16 h = __float2bfloat16(v);
    __nv_bfloat16 l = __float2bfloat16(v - __bfloat162float(h));
    Bh[(size_t)n * K + k] = h;
    Bl[(size_t)n * K + k] = l;
}

// ---------------- HMMA GEMM (BM=128, double-buffered, cp.async) ------------
// If Ch != nullptr: write fp16 to Ch (dinv-scaled). Else write fp32 to C.
__global__ void __launch_bounds__(256, 2)
hmma_gemm(const float *__restrict__ A,
          const __nv_bfloat16 *__restrict__ Bhg,
          const __nv_bfloat16 *__restrict__ Blg,
          const float *__restrict__ bias, const float *__restrict__ dinv,
          float *__restrict__ C, __half *__restrict__ Ch, int M, int K)
{
    extern __shared__ __align__(1024) char smem[];
    const uint32_t sb = s2u(smem);
    const int tid = threadIdx.x;
    const int wid = tid >> 5, lane = tid & 31;
    const int warp_m = wid & 3, warp_n = wid >> 2;
    const int bm0 = blockIdx.x * 128;

    const int alr = tid >> 1, alq = tid & 1;
    int arow = bm0 + alr; if (arow >= M) arow = M - 1;
    const float *Ar = A + (size_t)arow * K + alq * 16;
    const uint32_t a_sts = (uint32_t)(alr * ASTRIDE + alq * 32);

    const int bln = tid >> 1, blu = tid & 1;
    const __nv_bfloat16 *Bhr = Bhg + (size_t)bln * K + blu * 16;
    const __nv_bfloat16 *Blr = Blg + (size_t)bln * K + blu * 16;
    const uint32_t b_sts = (uint32_t)(bln * ASTRIDE + blu * 32);

    const int sub = lane >> 3, lr8 = lane & 7;
    uint32_t a_off[2], b_off[4];
#pragma unroll
    for (int mi = 0; mi < 2; ++mi) {
        int row = warp_m * 32 + mi * 16 + ((sub & 1) << 3) + lr8;
        a_off[mi] = (uint32_t)(row * ASTRIDE + ((sub >> 1) << 4));
    }
#pragma unroll
    for (int np = 0; np < 4; ++np) {
        int nr = warp_n * 64 + np * 16 + ((sub >> 1) << 3) + lr8;
        b_off[np] = (uint32_t)(nr * ASTRIDE + ((sub & 1) << 4));
    }

    float acc[2][8][4];
#pragma unroll
    for (int mi = 0; mi < 2; ++mi)
#pragma unroll
        for (int ni = 0; ni < 8; ++ni)
#pragma unroll
            for (int q = 0; q < 4; ++q) acc[mi][ni][q] = 0.f;

    const int NC = K / BK;
    float4 va0, va1, va2, va3;

    // ---- prologue ----
    va0 = *(const float4 *)(Ar);
    va1 = *(const float4 *)(Ar + 4);
    va2 = *(const float4 *)(Ar + 8);
    va3 = *(const float4 *)(Ar + 12);
    {
        uint32_t s0 = sb + 2 * ABUF + b_sts;
        cpa16(s0,             Bhr);
        cpa16(s0 + 16,        Bhr + 8);
        cpa16(s0 + BBUF,      Blr);
        cpa16(s0 + BBUF + 16, Blr + 8);
        asm volatile("cp.async.commit_group;" ::: "memory");
    }
    {
        uint4 hv, lv;
        cvt8(va0, va1, hv, lv);
        *(uint4 *)(smem + a_sts)        = hv;
        *(uint4 *)(smem + ABUF + a_sts) = lv;
        cvt8(va2, va3, hv, lv);
        *(uint4 *)(smem + a_sts + 16)        = hv;
        *(uint4 *)(smem + ABUF + a_sts + 16) = lv;
    }
    asm volatile("cp.async.wait_group 0;" ::: "memory");
    __syncthreads();

    for (int c = 0; c < NC; ++c) {
        const uint32_t bo = (c & 1) ? (uint32_t)BUFSZ : 0u;
        const uint32_t bn = (c & 1) ? 0u : (uint32_t)BUFSZ;
        const bool more = (c + 1 < NC);
        if (more) {
            const int k1 = (c + 1) * BK;
            va0 = *(const float4 *)(Ar + k1);
            va1 = *(const float4 *)(Ar + k1 + 4);
            va2 = *(const float4 *)(Ar + k1 + 8);
            va3 = *(const float4 *)(Ar + k1 + 12);
            uint32_t s0 = sb + bn + 2 * ABUF + b_sts;
            cpa16(s0,             Bhr + k1);
            cpa16(s0 + 16,        Bhr + k1 + 8);
            cpa16(s0 + BBUF,      Blr + k1);
            cpa16(s0 + BBUF + 16, Blr + k1 + 8);
            asm volatile("cp.async.commit_group;" ::: "memory");
        }

#pragma unroll
        for (int ks = 0; ks < 2; ++ks) {
            uint32_t ahi[2][4], alo[2][4];
#pragma unroll
            for (int mi = 0; mi < 2; ++mi) {
                uint32_t ad = sb + bo + a_off[mi] + ks * 32;
                ldsm4(ahi[mi][0], ahi[mi][1], ahi[mi][2], ahi[mi][3], ad);
                ldsm4(alo[mi][0], alo[mi][1], alo[mi][2], alo[mi][3], ad + ABUF);
            }
#pragma unroll
            for (int np = 0; np < 4; ++np) {
                uint32_t bhi[2][2], blo[2][2];
                uint32_t bd = sb + bo + 2 * ABUF + b_off[np] + ks * 32;
                ldsm4(bhi[0][0], bhi[0][1], bhi[1][0], bhi[1][1], bd);
                ldsm4(blo[0][0], blo[0][1], blo[1][0], blo[1][1], bd + BBUF);
#pragma unroll
                for (int mi = 0; mi < 2; ++mi)
#pragma unroll
                    for (int h = 0; h < 2; ++h)
                        mma16816(acc[mi][np * 2 + h], ahi[mi], bhi[h]);
#pragma unroll
                for (int mi = 0; mi < 2; ++mi)
#pragma unroll
                    for (int h = 0; h < 2; ++h)
                        mma16816(acc[mi][np * 2 + h], ahi[mi], blo[h]);
#pragma unroll
                for (int mi = 0; mi < 2; ++mi)
#pragma unroll
                    for (int h = 0; h < 2; ++h)
                        mma16816(acc[mi][np * 2 + h], alo[mi], bhi[h]);
            }
        }

        if (more) {
            uint4 hv, lv;
            cvt8(va0, va1, hv, lv);
            *(uint4 *)(smem + bn + a_sts)        = hv;
            *(uint4 *)(smem + bn + ABUF + a_sts) = lv;
            cvt8(va2, va3, hv, lv);
            *(uint4 *)(smem + bn + a_sts + 16)        = hv;
            *(uint4 *)(smem + bn + ABUF + a_sts + 16) = lv;
            asm volatile("cp.async.wait_group 0;" ::: "memory");
        }
        __syncthreads();
    }

    // ---- epilogue ----
    const int gid = lane >> 2, qid = lane & 3;
#pragma unroll
    for (int mi = 0; mi < 2; ++mi) {
        int row0 = bm0 + warp_m * 32 + mi * 16 + gid;
        int row1 = row0 + 8;
        float s0 = 1.f, s1 = 1.f;
        if (dinv) {
            if (row0 < M) s0 = dinv[row0];
            if (row1 < M) s1 = dinv[row1];
        }
#pragma unroll
        for (int ni = 0; ni < 8; ++ni) {
            int col = warp_n * 64 + ni * 8 + qid * 2;
            float b0 = 0.f, b1 = 0.f;
            if (bias) { b0 = bias[col]; b1 = bias[col + 1]; }
            float o00 = fmaf(acc[mi][ni][0], s0, b0);
            float o01 = fmaf(acc[mi][ni][1], s0, b1);
            float o10 = fmaf(acc[mi][ni][2], s1, b0);
            float o11 = fmaf(acc[mi][ni][3], s1, b1);
            if (Ch) {
                if (row0 < M) {
                    __half2 p = __floats2half2_rn(o00, o01);
                    *(uint32_t *)&Ch[(size_t)row0 * HID + col] = *(uint32_t *)&p;
                }
                if (row1 < M) {
                    __half2 p = __floats2half2_rn(o10, o11);
                    *(uint32_t *)&Ch[(size_t)row1 * HID + col] = *(uint32_t *)&p;
                }
            } else {
                if (row0 < M)
                    *(float2 *)&C[(size_t)row0 * HID + col] = make_float2(o00, o01);
                if (row1 < M)
                    *(float2 *)&C[(size_t)row1 * HID + col] = make_float2(o10, o11);
            }
        }
    }
}

// ---------------- CSR aggregate: warp per node (fp16 hs) -------------------
// hs pre-scaled by source dinv.  out = dinv_d*(sum + self) + bias
__device__ __forceinline__ void addh4(float4 &acc, uint2 raw) {
    __half2 p0 = *(__half2 *)&raw.x;
    __half2 p1 = *(__half2 *)&raw.y;
    float2 f0 = __half22float2(p0);
    float2 f1 = __half22float2(p1);
    acc.x += f0.x; acc.y += f0.y; acc.z += f1.x; acc.w += f1.y;
}
__global__ void __launch_bounds__(256)
k_agg(const __half *__restrict__ hs, const float *__restrict__ bias,
      float *__restrict__ outp, const int *__restrict__ batch,
      float *__restrict__ pool, int relu, int pool_mode, int N)
{
    int node = (blockIdx.x * blockDim.x + threadIdx.x) >> 5;
    if (node >= N) return;
    int lane = threadIdx.x & 31;
    int c = lane * 4;

    int e0 = g_start[node], e1 = g_start[node + 1];
    float4 acc = make_float4(0.f, 0.f, 0.f, 0.f);
    addh4(acc, *(const uint2 *)&hs[(size_t)node * HID + c]);   // self loop

    int e = e0;
    for (; e + 4 <= e1; e += 4) {
        int i0 = g_csr[e], i1 = g_csr[e + 1], i2 = g_csr[e + 2], i3 = g_csr[e + 3];
        uint2 r0 = *(const uint2 *)&hs[(size_t)i0 * HID + c];
        uint2 r1 = *(const uint2 *)&hs[(size_t)i1 * HID + c];
        uint2 r2 = *(const uint2 *)&hs[(size_t)i2 * HID + c];
        uint2 r3 = *(const uint2 *)&hs[(size_t)i3 * HID + c];
        addh4(acc, r0); addh4(acc, r1); addh4(acc, r2); addh4(acc, r3);
    }
    for (; e < e1; ++e) {
        int i0 = g_csr[e];
        addh4(acc, *(const uint2 *)&hs[(size_t)i0 * HID + c]);
    }

    float dv = g_dinv[node];
    float4 b = *(const float4 *)&bias[c];
    float4 o;
    o.x = fmaf(dv, acc.x, b.x);
    o.y = fmaf(dv, acc.y, b.y);
    o.z = fmaf(dv, acc.z, b.z);
    o.w = fmaf(dv, acc.w, b.w);
    if (relu) {
        o.x = fmaxf(o.x, 0.f); o.y = fmaxf(o.y, 0.f);
        o.z = fmaxf(o.z, 0.f); o.w = fmaxf(o.w, 0.f);
    }
    if (pool_mode) {
        int g = batch[node];
        red4(&pool[(size_t)g * HID + c], o);
        if (lane == 0) atomicAdd(&pool[NGRAPH * HID + g], 1.0f);
    } else {
        *(float4 *)&outp[(size_t)node * HID + c] = o;
    }
}

// ---------------- head MLP -------------------------------------------------
__global__ void k_head(const float *__restrict__ pool,
                       const float *__restrict__ W1, const float *__restrict__ b1,
                       const float *__restrict__ W2, const float *__restrict__ b2,
                       float *__restrict__ out)
{
    __shared__ float gv[HID];
    __shared__ float hid[HID];
    int g = blockIdx.x, t = threadIdx.x;
    float cnt = fmaxf(pool[NGRAPH * HID + g], 1.0f);
    gv[t] = pool[(size_t)g * HID + t] / cnt;
    __syncthreads();
    float acc = b1[t];
#pragma unroll 8
    for (int c = 0; c < HID; ++c) acc = fmaf(gv[c], W1[c * HID + t], acc);
    hid[t] = fmaxf(acc, 0.f);
    __syncthreads();
    if (t < NCLS) {
        float o = b2[t];
#pragma unroll 8
        for (int hh = 0; hh < HID; ++hh) o = fmaf(hid[hh], W2[hh * NCLS + t], o);
        out[g * NCLS + t] = o;
    }
}

// ---------------- launcher -------------------------------------------------
extern "C" void kernel_launch(void *const *d_in, const int *in_sizes, int n_in,
                              void *d_out, int out_size)
{
    const float *x     = (const float *)d_in[0];
    const int   *ei    = (const int *)d_in[1];
    const int   *batch = (const int *)d_in[2];
    const float *W_emb = (const float *)d_in[3], *b_emb = (const float *)d_in[4];
    const float *W_c1  = (const float *)d_in[5], *b_c1  = (const float *)d_in[6];
    const float *W_c2  = (const float *)d_in[7], *b_c2  = (const float *)d_in[8];
    const float *W_l1  = (const float *)d_in[9], *b_l1  = (const float *)d_in[10];
    const float *W_l2  = (const float *)d_in[11], *b_l2 = (const float *)d_in[12];
    float *out = (float *)d_out;

    const int E = in_sizes[1] / 2;
    const int N = in_sizes[2];
    const int K_IN = in_sizes[0] / N;

    static float *p_h = nullptr, *p_dinv = nullptr, *p_pool = nullptr;
    static __half *p_hsh = nullptr;
    static int *p_deg = nullptr;
    static __nv_bfloat16 *p_We_h, *p_We_l, *p_W1_h, *p_W1_l, *p_W2_h, *p_W2_l;
    static cudaStream_t s2 = nullptr;
    static cudaEvent_t evFork = nullptr, evJoin = nullptr;
    if (!p_h) {
        cudaGetSymbolAddress((void **)&p_h,    g_h);
        cudaGetSymbolAddress((void **)&p_hsh,  g_hsh);
        cudaGetSymbolAddress((void **)&p_dinv, g_dinv);
        cudaGetSymbolAddress((void **)&p_pool, g_pool);
        cudaGetSymbolAddress((void **)&p_deg,  g_deg);
        cudaGetSymbolAddress((void **)&p_We_h, g_Wemb_h);
        cudaGetSymbolAddress((void **)&p_We_l, g_Wemb_l);
        cudaGetSymbolAddress((void **)&p_W1_h, g_Wc1_h);
        cudaGetSymbolAddress((void **)&p_W1_l, g_Wc1_l);
        cudaGetSymbolAddress((void **)&p_W2_h, g_Wc2_h);
        cudaGetSymbolAddress((void **)&p_W2_l, g_Wc2_l);
        cudaFuncSetAttribute(hmma_gemm,
                             cudaFuncAttributeMaxDynamicSharedMemorySize, MMA_SMEM);
        cudaStreamCreateWithFlags(&s2, cudaStreamNonBlocking);
        cudaEventCreateWithFlags(&evFork, cudaEventDisableTiming);
        cudaEventCreateWithFlags(&evJoin, cudaEventDisableTiming);
    }

    const int mma_grid  = (N + 127) / 128;
    const int agg_grid  = (N * 32 + 255) / 256;

    // ---- fork: side chain on s2 ----
    cudaEventRecord(evFork, 0);
    cudaStreamWaitEvent(s2, evFork, 0);

    k_zero_deg<<<(N + 255) / 256, 256, 0, s2>>>(p_deg, N);
    k_deg <<<(E + 255) / 256, 256, 0, s2>>>(ei, E);
    k_dinv<<<(N + 255) / 256, 256, 0, s2>>>(N);
    k_scan1<<<NSCANB, 256, 0, s2>>>(N);
    k_scan2<<<1, 256, 0, s2>>>();
    k_scan3<<<(N + 255) / 256, 256, 0, s2>>>(N, E);
    k_fill <<<(E + 255) / 256, 256, 0, s2>>>(ei, E);
    k_prepW<<<(HID * HID + 255) / 256, 256, 0, s2>>>(W_c1, p_W1_h, p_W1_l, HID);
    k_prepW<<<(HID * HID + 255) / 256, 256, 0, s2>>>(W_c2, p_W2_h, p_W2_l, HID);
    k_zero4<<<(NGRAPH * (HID + 1) / 4 + 255) / 256, 256, 0, s2>>>(
        (float4 *)p_pool, NGRAPH * (HID + 1) / 4);

    // main chain: embedding GEMM (fp32 out)
    k_prepW<<<(K_IN * HID + 255) / 256, 256>>>(W_emb, p_We_h, p_We_l, K_IN);
    hmma_gemm<<<mma_grid, 256, MMA_SMEM>>>(x, p_We_h, p_We_l, b_emb, nullptr,
                                           p_h, nullptr, N, K_IN);

    // ---- join ----
    cudaEventRecord(evJoin, s2);
    cudaStreamWaitEvent(0, evJoin, 0);

    // conv1: hs(fp16) = dinv*(h0@Wc1); h1 = relu(dinv_d*(agg+self)+b)
    hmma_gemm<<<mma_grid, 256, MMA_SMEM>>>(p_h, p_W1_h, p_W1_l, nullptr, p_dinv,
                                           nullptr, p_hsh, N, HID);
    k_agg<<<agg_grid, 256>>>(p_hsh, b_c1, p_h, nullptr, nullptr, 1, 0, N);

    // conv2: hs(fp16) = dinv*(h1@Wc2); fused agg + global-mean-pool
    hmma_gemm<<<mma_grid, 256, MMA_SMEM>>>(p_h, p_W2_h, p_W2_l, nullptr, p_dinv,
                                           nullptr, p_hsh, N, HID);
    k_agg<<<agg_grid, 256>>>(p_hsh, b_c2, nullptr, batch, p_pool, 0, 1, N);

    // head
    k_head<<<NGRAPH, HID>>>(p_pool, W_l1, b_l1, W_l2, b_l2, out);
}